// round 10
// baseline (speedup 1.0000x reference)
#include <cuda_runtime.h>
#include <cuda_fp16.h>
#include <math.h>
#include <float.h>
#include <stdint.h>

// ============================================================================
// DeepSeekV3 MoE Gate (sm_103a; PTX target compute_103 -> no tcgen05).
// Fully fused: GEMM (mma.sync fp16x2 split, 3 passes, RN flush) + sigmoid/
// bias/grouped top-k in one kernel. CTA = 64 tokens x ALL 256 experts.
// R10: BK=32, 4-stage cp.async pipeline, single __syncthreads per chunk.
// Output (float32): [ T*8 indices (as float) | T*8 weights ]
// ============================================================================

#define N_EXPERTS 256
#define TOPK_GRP  4
#define TOP_K     8
#define SCALE     2.5f
#define H_DIM     7168
#define W_PRESCALE   64.0f
#define W_POSTSCALE  0.015625f   // 1/64

__device__ __align__(16) __half g_wh[N_EXPERTS * H_DIM];      // fp16(64*w)
__device__ __align__(16) __half g_wm[N_EXPERTS * H_DIM];      // fp16(64*w - hi)

// ---------------------------------------------------------------------------
// helpers
// ---------------------------------------------------------------------------
__device__ __forceinline__ uint32_t smem_to_u32(const void* p) {
    uint32_t a;
    asm("{ .reg .u64 t; cvta.to.shared.u64 t, %1; cvt.u32.u64 %0, t; }"
        : "=r"(a) : "l"(p));
    return a;
}
__device__ __forceinline__ void cp16(uint32_t dst, const void* src) {
    asm volatile("cp.async.cg.shared.global [%0], [%1], 16;" :: "r"(dst), "l"(src));
}
#define CP_COMMIT() asm volatile("cp.async.commit_group;" ::: "memory")
#define CP_WAIT2()  asm volatile("cp.async.wait_group 2;" ::: "memory")
#define CP_WAIT1()  asm volatile("cp.async.wait_group 1;" ::: "memory")
#define CP_WAIT0()  asm volatile("cp.async.wait_group 0;" ::: "memory")

__device__ __forceinline__ void ldmatrix_x4(uint32_t* r, uint32_t addr) {
    asm volatile("ldmatrix.sync.aligned.m8n8.x4.shared.b16 {%0,%1,%2,%3}, [%4];"
                 : "=r"(r[0]), "=r"(r[1]), "=r"(r[2]), "=r"(r[3]) : "r"(addr));
}
__device__ __forceinline__ void mma_fp16(float* d, const uint32_t* a,
                                         uint32_t b0, uint32_t b1) {
    asm volatile(
        "mma.sync.aligned.m16n8k16.row.col.f32.f16.f16.f32 "
        "{%0,%1,%2,%3}, {%4,%5,%6,%7}, {%8,%9}, {%0,%1,%2,%3};"
        : "+f"(d[0]), "+f"(d[1]), "+f"(d[2]), "+f"(d[3])
        : "r"(a[0]), "r"(a[1]), "r"(a[2]), "r"(a[3]), "r"(b0), "r"(b1));
}

// split a float2 into 2 packed fp16x2 (hi, mid); low 16 bits = f.x
__device__ __forceinline__ void split2(float2 f, uint32_t& h, uint32_t& m) {
    __half2 hh = __floats2half2_rn(f.x, f.y);
    h = *reinterpret_cast<uint32_t*>(&hh);
    float2 hf = __half22float2(hh);
    __half2 mm2 = __floats2half2_rn(f.x - hf.x, f.y - hf.y);
    m = *reinterpret_cast<uint32_t*>(&mm2);
}

// ---------------------------------------------------------------------------
// Kernel 0: split prescaled fp32 weights -> 2 fp16 tensors
// ---------------------------------------------------------------------------
__global__ __launch_bounds__(256)
void split_w_kernel(const float* __restrict__ w)
{
    int i = blockIdx.x * 256 + threadIdx.x;           // one float4 per thread
    const int n4 = N_EXPERTS * H_DIM / 4;
    if (i >= n4) return;
    float4 v = reinterpret_cast<const float4*>(w)[i];
    uint32_t h0, m0, h1, m1;
    split2(make_float2(v.x * W_PRESCALE, v.y * W_PRESCALE), h0, m0);
    split2(make_float2(v.z * W_PRESCALE, v.w * W_PRESCALE), h1, m1);
    reinterpret_cast<uint2*>(g_wh)[i] = make_uint2(h0, h1);
    reinterpret_cast<uint2*>(g_wm)[i] = make_uint2(m0, m1);
}

// ---------------------------------------------------------------------------
// Fused kernel: GEMM + sigmoid/bias/grouped top-k.
// CTA: 64 tokens x 256 experts. BK=32. 4-stage cp.async pipeline. 1 CTA/SM.
// warps: 2(m) x 4(n); warp tile 32 x 64; accum 2x8 m16n8 microtiles.
// smem/stage: A fp32 [64][40] (160B rows), B fp16x2 [2][256][80B rows]
// ---------------------------------------------------------------------------
#define BM        64
#define BN        256
#define BK        32
#define NCHUNK    (H_DIM / BK)          // 224
#define FLUSH_MASK 7                    // flush every 8 chunks (K=256)
#define A_ROWB    160                   // 40 floats
#define A_BYTES   (64 * A_ROWB)         // 10240
#define B_ROWB    80
#define B_SPLIT_B (256 * B_ROWB)        // 20480
#define STAGE_B   (A_BYTES + 2 * B_SPLIT_B)  // 51200
#define NSTAGE    4
#define GEMM_SMEM (NSTAGE * STAGE_B)         // 204800
#define LG_STRIDE 260                   // fp32 row stride for epilogue logits

__device__ __forceinline__ void load_stage(const float* __restrict__ x,
                                           int row0, int k0,
                                           uint32_t stage_base, int tid)
{
    // A: 64 rows x 32 fp32 (128B payload/row, stride 160B): 512 cp16
#pragma unroll
    for (int l = 0; l < 2; l++) {
        int q = tid + 256 * l;             // 0..511
        int row = q >> 3, seg = q & 7;
        const float* src = x + (size_t)(row0 + row) * H_DIM + k0 + seg * 4;
        cp16(stage_base + row * A_ROWB + seg * 16, src);
    }
    // B: 2 splits x 256 rows x 32 fp16 (64B payload/row, stride 80B): 2048 cp16
#pragma unroll
    for (int l = 0; l < 8; l++) {
        int q = tid + 256 * l;             // 0..2047
        int s = q >> 10;                   // split
        int r = q & 1023;
        int row = r >> 2, seg = r & 3;
        const __half* wp = s ? g_wm : g_wh;
        const __half* src = wp + (size_t)row * H_DIM + k0 + seg * 8;
        cp16(stage_base + A_BYTES + s * B_SPLIT_B + row * B_ROWB + seg * 16, src);
    }
}

__global__ __launch_bounds__(256, 1)
void moe_fused_kernel(const float* __restrict__ x,
                      const float* __restrict__ bias,
                      float* __restrict__ out, int T)
{
    extern __shared__ char smem[];
    const uint32_t sbase = smem_to_u32(smem);
    const int tid  = threadIdx.x;
    const int lane = tid & 31;
    const int wid  = tid >> 5;
    const int wm   = wid & 1;              // warp row (m): 0..1
    const int wn   = wid >> 1;             // warp col (n): 0..3
    const int row0 = blockIdx.x * BM;

    float acc[2][8][4];                    // short-chain accumulators
    float master[2][8][4];                 // RN-summed masters
#pragma unroll
    for (int mt = 0; mt < 2; mt++)
#pragma unroll
        for (int nt = 0; nt < 8; nt++)
#pragma unroll
            for (int q = 0; q < 4; q++) { acc[mt][nt][q] = 0.0f; master[mt][nt][q] = 0.0f; }

    // prologue: stages 0..2
    load_stage(x, row0, 0 * BK, sbase + 0 * STAGE_B, tid); CP_COMMIT();
    load_stage(x, row0, 1 * BK, sbase + 1 * STAGE_B, tid); CP_COMMIT();
    load_stage(x, row0, 2 * BK, sbase + 2 * STAGE_B, tid); CP_COMMIT();

    const int c2 = (lane & 3) * 2;         // k-pair base within 8

    for (int c = 0; c < NCHUNK; ++c) {
        // wait for stage c
        if (c < NCHUNK - 2)      { CP_WAIT2(); }
        else if (c == NCHUNK - 2){ CP_WAIT1(); }
        else                     { CP_WAIT0(); }
        __syncthreads();           // everyone done with slot (c-1); stage c visible

        // issue load for stage c+3 into slot (c+3)%4 (overwrites slot c-1)
        if (c + 3 < NCHUNK) {
            load_stage(x, row0, (c + 3) * BK, sbase + ((c + 3) & 3) * STAGE_B, tid);
            CP_COMMIT();
        }

        const int slot = c & 3;
        const char* As = smem + slot * STAGE_B;
        const uint32_t Bs = sbase + slot * STAGE_B + A_BYTES;

#pragma unroll
        for (int kk = 0; kk < 2; kk++) {           // two k16 steps per BK=32
            // ---- A fragments: load fp32 pairs, split to fp16x2 ----
            uint32_t ah[2][4], am[2][4];
#pragma unroll
            for (int mt = 0; mt < 2; mt++) {
                int brow = wm * 32 + mt * 16 + (lane >> 2);
#pragma unroll
                for (int q = 0; q < 4; q++) {
                    int r   = brow + (q & 1) * 8;
                    int col = kk * 16 + c2 + (q >> 1) * 8;
                    float2 f = *reinterpret_cast<const float2*>(As + r * A_ROWB + col * 4);
                    split2(f, ah[mt][q], am[mt][q]);
                }
            }
            // ---- 3 passes: s=0 -> ah*bh + am*bh ; s=1 -> ah*bm ----
#pragma unroll
            for (int s = 0; s < 2; s++) {
                uint32_t b[4][4];
#pragma unroll
                for (int p = 0; p < 4; p++) {
                    int row = wn * 64 + p * 16 + (lane & 7) + ((lane >> 4) & 1) * 8;
                    uint32_t addr = Bs + s * B_SPLIT_B + row * B_ROWB
                                  + kk * 32 + ((lane >> 3) & 1) * 16;
                    ldmatrix_x4(b[p], addr);
                }
#pragma unroll
                for (int mt = 0; mt < 2; mt++)
#pragma unroll
                    for (int nt = 0; nt < 8; nt++) {
                        int p = nt >> 1, o = (nt & 1) * 2;
                        mma_fp16(acc[mt][nt], ah[mt], b[p][o], b[p][o + 1]);
                    }
                if (s == 0) {
#pragma unroll
                    for (int mt = 0; mt < 2; mt++)
#pragma unroll
                        for (int nt = 0; nt < 8; nt++) {
                            int p = nt >> 1, o = (nt & 1) * 2;
                            mma_fp16(acc[mt][nt], am[mt], b[p][o], b[p][o + 1]);
                        }
                }
            }
        }

        // ---- RN flush: keep tensor-core accumulation chains short ----
        if ((c & FLUSH_MASK) == FLUSH_MASK) {
#pragma unroll
            for (int mt = 0; mt < 2; mt++)
#pragma unroll
                for (int nt = 0; nt < 8; nt++)
#pragma unroll
                    for (int q = 0; q < 4; q++) {
                        master[mt][nt][q] += acc[mt][nt][q];
                        acc[mt][nt][q] = 0.0f;
                    }
        }
    }

    // fold residual (NCHUNK % 8 == 0 -> acc already zero, harmless)
#pragma unroll
    for (int mt = 0; mt < 2; mt++)
#pragma unroll
        for (int nt = 0; nt < 8; nt++)
#pragma unroll
            for (int q = 0; q < 4; q++) master[mt][nt][q] += acc[mt][nt][q];

    // ---- write logits to smem [64][LG_STRIDE] (undo W prescale) ----
    float* lgs = reinterpret_cast<float*>(smem);
    __syncthreads();   // all compute done; safe to repurpose smem
#pragma unroll
    for (int mt = 0; mt < 2; mt++) {
        int row = wm * 32 + mt * 16 + (lane >> 2);
#pragma unroll
        for (int nt = 0; nt < 8; nt++) {
            int col = wn * 64 + nt * 8 + c2;
            *reinterpret_cast<float2*>(&lgs[row * LG_STRIDE + col]) =
                make_float2(master[mt][nt][0] * W_POSTSCALE,
                            master[mt][nt][1] * W_POSTSCALE);
            *reinterpret_cast<float2*>(&lgs[(row + 8) * LG_STRIDE + col]) =
                make_float2(master[mt][nt][2] * W_POSTSCALE,
                            master[mt][nt][3] * W_POSTSCALE);
        }
    }
    __syncthreads();

    // ---- fused grouped top-k: warp w handles tokens w*8 .. w*8+7 ----
    const unsigned FULL = 0xFFFFFFFFu;
    const float bias_l[8] = {
        bias[0 * 32 + lane], bias[1 * 32 + lane], bias[2 * 32 + lane],
        bias[3 * 32 + lane], bias[4 * 32 + lane], bias[5 * 32 + lane],
        bias[6 * 32 + lane], bias[7 * 32 + lane]
    };

    for (int ti = 0; ti < 8; ti++) {
        const int tl = wid * 8 + ti;           // token within CTA
        const int t  = row0 + tl;              // global token
        const float* lg = &lgs[tl * LG_STRIDE];

        float s[8], sb[8];
#pragma unroll
        for (int j = 0; j < 8; j++) {
            float logit = lg[j * 32 + lane];
            float sv = 1.0f / (1.0f + expf(-logit));
            s[j]  = sv;
            sb[j] = sv + bias_l[j];
        }

        float gs[8];
#pragma unroll
        for (int g = 0; g < 8; g++) {
            float m1 = sb[g], m2 = -FLT_MAX;
#pragma unroll
            for (int off = 16; off >= 1; off >>= 1) {
                float o1 = __shfl_xor_sync(FULL, m1, off);
                float o2 = __shfl_xor_sync(FULL, m2, off);
                float hi = fmaxf(m1, o1);
                float lo = fminf(m1, o1);
                m2 = fmaxf(lo, fmaxf(m2, o2));
                m1 = hi;
            }
            gs[g] = m1 + m2;
        }

        unsigned gmask = 0;
#pragma unroll
        for (int r = 0; r < TOPK_GRP; r++) {
            float best = -FLT_MAX; int bg = 0;
#pragma unroll
            for (int g = 0; g < 8; g++) {
                bool taken = (gmask >> g) & 1u;
                if (!taken && gs[g] > best) { best = gs[g]; bg = g; }
            }
            gmask |= (1u << bg);
        }

        float v[8];
#pragma unroll
        for (int j = 0; j < 8; j++)
            v[j] = ((gmask >> j) & 1u) ? sb[j] : -FLT_MAX;

        float wts[TOP_K];
        int   idxs[TOP_K];
        float wsum = 0.0f;
#pragma unroll
        for (int r = 0; r < TOP_K; r++) {
            float bv = -FLT_MAX; int bj = -1;
#pragma unroll
            for (int j = 0; j < 8; j++)
                if (v[j] > bv) { bv = v[j]; bj = j; }
            int bidx = (bj >= 0) ? (bj * 32 + lane) : (N_EXPERTS + lane);

            float cv = bv; int ci = bidx;
#pragma unroll
            for (int off = 16; off >= 1; off >>= 1) {
                float ov = __shfl_xor_sync(FULL, cv, off);
                int   oi = __shfl_xor_sync(FULL, ci, off);
                if (ov > cv || (ov == cv && oi < ci)) { cv = ov; ci = oi; }
            }
            int wl = ci & 31;
            int wj = ci >> 5;
            float sv_local = 0.0f;
#pragma unroll
            for (int j = 0; j < 8; j++) if (j == wj) sv_local = s[j];
            float sv = __shfl_sync(FULL, sv_local, wl);

            idxs[r] = ci;
            wts[r]  = sv;
            wsum   += sv;

            if (lane == wl) {
#pragma unroll
                for (int j = 0; j < 8; j++) if (j == wj) v[j] = -FLT_MAX;
            }
        }

        if (lane == 0) {
            float inv = SCALE / wsum;
            size_t half = (size_t)T * TOP_K;
#pragma unroll
            for (int r = 0; r < TOP_K; r++) {
                out[(size_t)t * TOP_K + r]        = (float)idxs[r];
                out[half + (size_t)t * TOP_K + r] = wts[r] * inv;
            }
        }
    }
}

// ---------------------------------------------------------------------------
extern "C" void kernel_launch(void* const* d_in, const int* in_sizes, int n_in,
                              void* d_out, int out_size)
{
    const float* x    = (const float*)d_in[0];   // [B,S,H] fp32
    const float* w    = (const float*)d_in[1];   // [E,H]   fp32
    const float* bias = (const float*)d_in[2];   // [E]     fp32
    float* out = (float*)d_out;

    const int E = in_sizes[2];                   // 256
    const int H = in_sizes[1] / E;               // 7168
    const int T = in_sizes[0] / H;               // 8192

    // 0) split prescaled weights into fp16x2
    {
        int n4 = E * H / 4;
        split_w_kernel<<<(n4 + 255) / 256, 256>>>(w);
    }

    // 1) fused GEMM + topk
    cudaFuncSetAttribute(moe_fused_kernel,
                         cudaFuncAttributeMaxDynamicSharedMemorySize, GEMM_SMEM);
    moe_fused_kernel<<<T / BM, 256, GEMM_SMEM>>>(x, bias, out, T);
}

// round 11
// speedup vs baseline: 1.2710x; 1.2710x over previous
#include <cuda_runtime.h>
#include <cuda_fp16.h>
#include <math.h>
#include <float.h>
#include <stdint.h>

// ============================================================================
// DeepSeekV3 MoE Gate (sm_103a; PTX target compute_103 -> no tcgen05).
// GEMM via mma.sync.m16n8k16 fp16, fp16x2 split, 3 passes (hh, hm, mh),
// W prescaled x64 (single fp32 accumulator), periodic RN master flush.
// R11: revert to proven R7 split-kernel structure; optimize topk (redux
// group-top2 + __expf) and split_w (2x ILP).
//   logits = x @ W^T  (T=8192, H=7168, E=256)
// Output (float32): [ T*8 indices (as float) | T*8 weights ]
// ============================================================================

#define N_EXPERTS 256
#define TOPK_GRP  4
#define TOP_K     8
#define SCALE     2.5f
#define H_DIM     7168
#define MAX_T     8192
#define W_PRESCALE   64.0f
#define W_POSTSCALE  0.015625f   // 1/64

__device__ float g_logits[MAX_T * N_EXPERTS];                 // 8 MB
__device__ __align__(16) __half g_wh[N_EXPERTS * H_DIM];      // fp16(64*w)
__device__ __align__(16) __half g_wm[N_EXPERTS * H_DIM];      // fp16(64*w - hi)

// ---------------------------------------------------------------------------
// helpers
// ---------------------------------------------------------------------------
__device__ __forceinline__ uint32_t smem_to_u32(const void* p) {
    uint32_t a;
    asm("{ .reg .u64 t; cvta.to.shared.u64 t, %1; cvt.u32.u64 %0, t; }"
        : "=r"(a) : "l"(p));
    return a;
}
__device__ __forceinline__ void cp16(uint32_t dst, const void* src) {
    asm volatile("cp.async.cg.shared.global [%0], [%1], 16;" :: "r"(dst), "l"(src));
}
#define CP_COMMIT() asm volatile("cp.async.commit_group;" ::: "memory")
#define CP_WAIT1()  asm volatile("cp.async.wait_group 1;" ::: "memory")

__device__ __forceinline__ void ldmatrix_x4(uint32_t* r, uint32_t addr) {
    asm volatile("ldmatrix.sync.aligned.m8n8.x4.shared.b16 {%0,%1,%2,%3}, [%4];"
                 : "=r"(r[0]), "=r"(r[1]), "=r"(r[2]), "=r"(r[3]) : "r"(addr));
}
__device__ __forceinline__ void mma_fp16(float* d, const uint32_t* a,
                                         uint32_t b0, uint32_t b1) {
    asm volatile(
        "mma.sync.aligned.m16n8k16.row.col.f32.f16.f16.f32 "
        "{%0,%1,%2,%3}, {%4,%5,%6,%7}, {%8,%9}, {%0,%1,%2,%3};"
        : "+f"(d[0]), "+f"(d[1]), "+f"(d[2]), "+f"(d[3])
        : "r"(a[0]), "r"(a[1]), "r"(a[2]), "r"(a[3]), "r"(b0), "r"(b1));
}

// split a float2 into 2 packed fp16x2 (hi, mid); low 16 bits = f.x
__device__ __forceinline__ void split2(float2 f, uint32_t& h, uint32_t& m) {
    __half2 hh = __floats2half2_rn(f.x, f.y);
    h = *reinterpret_cast<uint32_t*>(&hh);
    float2 hf = __half22float2(hh);
    __half2 mm2 = __floats2half2_rn(f.x - hf.x, f.y - hf.y);
    m = *reinterpret_cast<uint32_t*>(&mm2);
}

// monotone float <-> unsigned-comparable key
__device__ __forceinline__ unsigned f2ord(float f) {
    unsigned u = __float_as_uint(f);
    return u ^ ((((int)u) >> 31) | 0x80000000u);
}
__device__ __forceinline__ float ord2f(unsigned k) {
    unsigned u = (k & 0x80000000u) ? (k ^ 0x80000000u) : ~k;
    return __uint_as_float(u);
}

// ---------------------------------------------------------------------------
// Kernel 0: split prescaled fp32 weights -> 2 fp16 tensors (2 float4/thread)
// ---------------------------------------------------------------------------
__global__ __launch_bounds__(256)
void split_w_kernel(const float* __restrict__ w)
{
    const int n4 = N_EXPERTS * H_DIM / 4;
    int base = blockIdx.x * 512 + threadIdx.x;
#pragma unroll
    for (int r = 0; r < 2; r++) {
        int i = base + r * 256;
        if (i >= n4) break;
        float4 v = reinterpret_cast<const float4*>(w)[i];
        uint32_t h0, m0, h1, m1;
        split2(make_float2(v.x * W_PRESCALE, v.y * W_PRESCALE), h0, m0);
        split2(make_float2(v.z * W_PRESCALE, v.w * W_PRESCALE), h1, m1);
        reinterpret_cast<uint2*>(g_wh)[i] = make_uint2(h0, h1);
        reinterpret_cast<uint2*>(g_wm)[i] = make_uint2(m0, m1);
    }
}

// ---------------------------------------------------------------------------
// Kernel 1: GEMM via mma.sync fp16x2, 3 passes, single accumulator + RN flush.
// CTA: 128 tokens x 128 experts. BK=64. 3-stage cp.async pipeline. 1 CTA/SM.
// smem/stage: A fp32 [128][72] (288B rows), B fp16x2 [2][128][144B rows]
// warps: 4(m) x 2(n); warp tile 32 x 64; accum 2x8 m16n8 microtiles.
// (PROVEN R7 structure — do not modify.)
// ---------------------------------------------------------------------------
#define BM        128
#define BN        128
#define BK        64
#define NCHUNK    (H_DIM / BK)          // 112
#define FLUSH_MASK 3                    // flush every 4 chunks (K=256)
#define A_ROWB    288                   // 72 floats
#define A_BYTES   (128 * A_ROWB)        // 36864
#define B_ROWB    144
#define B_SPLIT_B (128 * B_ROWB)        // 18432
#define STAGE_B   (A_BYTES + 2 * B_SPLIT_B)  // 73728
#define GEMM_SMEM (3 * STAGE_B)              // 221184

__device__ __forceinline__ void load_stage(const float* __restrict__ x,
                                           int row0, int e0, int k0,
                                           uint32_t stage_base, int tid)
{
    // A: 128 rows x 64 fp32 (256B payload/row, stride 288B): 2048 cp16
#pragma unroll
    for (int l = 0; l < 8; l++) {
        int q = tid + 256 * l;             // 0..2047
        int row = q >> 4, seg = q & 15;
        const float* src = x + (size_t)(row0 + row) * H_DIM + k0 + seg * 4;
        cp16(stage_base + row * A_ROWB + seg * 16, src);
    }
    // B: 2 splits x 128 rows x 64 fp16 (128B payload/row, stride 144B): 2048 cp16
#pragma unroll
    for (int l = 0; l < 8; l++) {
        int q = tid + 256 * l;             // 0..2047
        int s = q >> 10;                   // split
        int r = q & 1023;
        int row = r >> 3, seg = r & 7;
        const __half* wp = s ? g_wm : g_wh;
        const __half* src = wp + (size_t)(e0 + row) * H_DIM + k0 + seg * 8;
        cp16(stage_base + A_BYTES + s * B_SPLIT_B + row * B_ROWB + seg * 16, src);
    }
}

__global__ __launch_bounds__(256, 1)
void moe_gemm_mma(const float* __restrict__ x)
{
    extern __shared__ char smem[];
    const uint32_t sbase = smem_to_u32(smem);
    const int tid  = threadIdx.x;
    const int lane = tid & 31;
    const int wid  = tid >> 5;
    const int wm   = wid & 3;              // warp row (m)
    const int wn   = wid >> 2;             // warp col (n)
    const int row0 = blockIdx.x * BM;
    const int e0   = blockIdx.y * BN;

    float acc[2][8][4];                    // short-chain accumulators
    float master[2][8][4];                 // RN-summed masters
#pragma unroll
    for (int mt = 0; mt < 2; mt++)
#pragma unroll
        for (int nt = 0; nt < 8; nt++)
#pragma unroll
            for (int q = 0; q < 4; q++) { acc[mt][nt][q] = 0.0f; master[mt][nt][q] = 0.0f; }

    // prologue: stages 0,1
    load_stage(x, row0, e0, 0,  sbase + 0 * STAGE_B, tid); CP_COMMIT();
    load_stage(x, row0, e0, BK, sbase + 1 * STAGE_B, tid); CP_COMMIT();

    const int c2 = (lane & 3) * 2;         // k-pair base within 8

    for (int c = 0; c < NCHUNK; ++c) {
        CP_WAIT1();
        __syncthreads();

        if (c + 2 < NCHUNK)
            load_stage(x, row0, e0, (c + 2) * BK, sbase + ((c + 2) % 3) * STAGE_B, tid);
        CP_COMMIT();

        const int slot = c % 3;
        const char* As = smem + slot * STAGE_B;
        const uint32_t Bs = sbase + slot * STAGE_B + A_BYTES;

#pragma unroll
        for (int kk = 0; kk < 4; kk++) {           // four k16 steps per BK=64
            // ---- A fragments: load fp32 pairs, split to fp16x2 ----
            uint32_t ah[2][4], am[2][4];
#pragma unroll
            for (int mt = 0; mt < 2; mt++) {
                int brow = wm * 32 + mt * 16 + (lane >> 2);
#pragma unroll
                for (int q = 0; q < 4; q++) {
                    int r   = brow + (q & 1) * 8;
                    int col = kk * 16 + c2 + (q >> 1) * 8;
                    float2 f = *reinterpret_cast<const float2*>(As + r * A_ROWB + col * 4);
                    split2(f, ah[mt][q], am[mt][q]);
                }
            }
            // ---- 3 passes: s=0 -> ah*bh + am*bh ; s=1 -> ah*bm ----
#pragma unroll
            for (int s = 0; s < 2; s++) {
                uint32_t b[4][4];
#pragma unroll
                for (int p = 0; p < 4; p++) {
                    int row = wn * 64 + p * 16 + (lane & 7) + ((lane >> 4) & 1) * 8;
                    uint32_t addr = Bs + s * B_SPLIT_B + row * B_ROWB
                                  + kk * 32 + ((lane >> 3) & 1) * 16;
                    ldmatrix_x4(b[p], addr);
                }
#pragma unroll
                for (int mt = 0; mt < 2; mt++)
#pragma unroll
                    for (int nt = 0; nt < 8; nt++) {
                        int p = nt >> 1, o = (nt & 1) * 2;
                        mma_fp16(acc[mt][nt], ah[mt], b[p][o], b[p][o + 1]);
                    }
                if (s == 0) {
#pragma unroll
                    for (int mt = 0; mt < 2; mt++)
#pragma unroll
                        for (int nt = 0; nt < 8; nt++) {
                            int p = nt >> 1, o = (nt & 1) * 2;
                            mma_fp16(acc[mt][nt], am[mt], b[p][o], b[p][o + 1]);
                        }
                }
            }
        }

        // ---- RN flush: keep tensor-core accumulation chains short ----
        if ((c & FLUSH_MASK) == FLUSH_MASK) {
#pragma unroll
            for (int mt = 0; mt < 2; mt++)
#pragma unroll
                for (int nt = 0; nt < 8; nt++)
#pragma unroll
                    for (int q = 0; q < 4; q++) {
                        master[mt][nt][q] += acc[mt][nt][q];
                        acc[mt][nt][q] = 0.0f;
                    }
        }
    }

    // fold residual (NCHUNK % 4 == 0 -> acc already zero, harmless)
#pragma unroll
    for (int mt = 0; mt < 2; mt++)
#pragma unroll
        for (int nt = 0; nt < 8; nt++)
#pragma unroll
            for (int q = 0; q < 4; q++) master[mt][nt][q] += acc[mt][nt][q];

    // epilogue: write logits (undo W prescale)
#pragma unroll
    for (int mt = 0; mt < 2; mt++) {
        int row = row0 + wm * 32 + mt * 16 + (lane >> 2);
#pragma unroll
        for (int nt = 0; nt < 8; nt++) {
            int col = e0 + wn * 64 + nt * 8 + c2;
            *reinterpret_cast<float2*>(&g_logits[(size_t)row * N_EXPERTS + col]) =
                make_float2(master[mt][nt][0] * W_POSTSCALE,
                            master[mt][nt][1] * W_POSTSCALE);
            *reinterpret_cast<float2*>(&g_logits[(size_t)(row + 8) * N_EXPERTS + col]) =
                make_float2(master[mt][nt][2] * W_POSTSCALE,
                            master[mt][nt][3] * W_POSTSCALE);
        }
    }
}

// ---------------------------------------------------------------------------
// Kernel 2: per-token grouped top-k. One warp per token.
// R11: __expf sigmoid + REDUX-based group top-2 (tie-insensitive sum);
// argmax rounds keep exact compare tie-break (tie -> lower expert index).
// ---------------------------------------------------------------------------
__global__ __launch_bounds__(256)
void moe_topk_kernel(const float* __restrict__ bias, float* __restrict__ out, int T)
{
    const unsigned FULL = 0xFFFFFFFFu;
    const int lane   = threadIdx.x & 31;
    const int warpId = threadIdx.x >> 5;
    const int t = blockIdx.x * 8 + warpId;
    if (t >= T) return;

    const float* lg = &g_logits[(size_t)t * N_EXPERTS];

    float s[8], sb[8];
#pragma unroll
    for (int j = 0; j < 8; j++) {
        int e = j * 32 + lane;
        float logit = lg[e];
        float sv = 1.0f / (1.0f + __expf(-logit));
        s[j]  = sv;
        sb[j] = sv + bias[e];
    }

    // per-group top-2 sum via REDUX (sum is tie-insensitive)
    float gs[8];
#pragma unroll
    for (int g = 0; g < 8; g++) {
        unsigned k = f2ord(sb[g]);
        unsigned m1 = __reduce_max_sync(FULL, k);
        unsigned bal = __ballot_sync(FULL, k == m1);
        int leader = __ffs(bal) - 1;
        unsigned k2 = (lane == leader) ? 0u : k;
        unsigned m2 = __reduce_max_sync(FULL, k2);
        gs[g] = ord2f(m1) + ord2f(m2);
    }

    unsigned gmask = 0;
#pragma unroll
    for (int r = 0; r < TOPK_GRP; r++) {
        float best = -FLT_MAX; int bg = 0;
#pragma unroll
        for (int g = 0; g < 8; g++) {
            bool taken = (gmask >> g) & 1u;
            if (!taken && gs[g] > best) { best = gs[g]; bg = g; }
        }
        gmask |= (1u << bg);
    }

    float v[8];
#pragma unroll
    for (int j = 0; j < 8; j++)
        v[j] = ((gmask >> j) & 1u) ? sb[j] : -FLT_MAX;

    float wts[TOP_K];
    int   idxs[TOP_K];
    float wsum = 0.0f;
#pragma unroll
    for (int r = 0; r < TOP_K; r++) {
        float bv = -FLT_MAX; int bj = -1;
#pragma unroll
        for (int j = 0; j < 8; j++)
            if (v[j] > bv) { bv = v[j]; bj = j; }
        int bidx = (bj >= 0) ? (bj * 32 + lane) : (N_EXPERTS + lane);

        float cv = bv; int ci = bidx;
#pragma unroll
        for (int off = 16; off >= 1; off >>= 1) {
            float ov = __shfl_xor_sync(FULL, cv, off);
            int   oi = __shfl_xor_sync(FULL, ci, off);
            if (ov > cv || (ov == cv && oi < ci)) { cv = ov; ci = oi; }
        }
        int wl = ci & 31;
        int wj = ci >> 5;
        float sv_local = 0.0f;
#pragma unroll
        for (int j = 0; j < 8; j++) if (j == wj) sv_local = s[j];
        float sv = __shfl_sync(FULL, sv_local, wl);

        idxs[r] = ci;
        wts[r]  = sv;
        wsum   += sv;

        if (lane == wl) {
#pragma unroll
            for (int j = 0; j < 8; j++) if (j == wj) v[j] = -FLT_MAX;
        }
    }

    if (lane == 0) {
        float inv = SCALE / wsum;
        size_t half = (size_t)T * TOP_K;
#pragma unroll
        for (int r = 0; r < TOP_K; r++) {
            out[(size_t)t * TOP_K + r]        = (float)idxs[r];
            out[half + (size_t)t * TOP_K + r] = wts[r] * inv;
        }
    }
}

// ---------------------------------------------------------------------------
extern "C" void kernel_launch(void* const* d_in, const int* in_sizes, int n_in,
                              void* d_out, int out_size)
{
    const float* x    = (const float*)d_in[0];   // [B,S,H] fp32
    const float* w    = (const float*)d_in[1];   // [E,H]   fp32
    const float* bias = (const float*)d_in[2];   // [E]     fp32
    float* out = (float*)d_out;

    const int E = in_sizes[2];                   // 256
    const int H = in_sizes[1] / E;               // 7168
    const int T = in_sizes[0] / H;               // 8192

    // 0) split prescaled weights into fp16x2 (2 float4 per thread)
    {
        int n4 = E * H / 4;
        split_w_kernel<<<(n4 + 511) / 512, 256>>>(w);
    }

    // 1) tensor-core GEMM -> g_logits
    cudaFuncSetAttribute(moe_gemm_mma,
                         cudaFuncAttributeMaxDynamicSharedMemorySize, GEMM_SMEM);
    dim3 gemmGrid(T / BM, E / BN);               // (64, 2)
    moe_gemm_mma<<<gemmGrid, 256, GEMM_SMEM>>>(x);

    // 2) grouped top-k
    dim3 topkGrid((T + 7) / 8);
    moe_topk_kernel<<<topkGrid, 256>>>(bias, out, T);
}

// round 12
// speedup vs baseline: 1.4169x; 1.1148x over previous
#include <cuda_runtime.h>
#include <cuda_fp16.h>
#include <math.h>
#include <float.h>
#include <stdint.h>

// ============================================================================
// DeepSeekV3 MoE Gate (sm_103a; PTX target compute_103 -> no tcgen05).
// GEMM via mma.sync.m16n8k16 fp16, fp16x2 split, 3 passes (hh, hm, mh),
// W prescaled x64 (single fp32 accumulator), periodic RN master flush.
// R12: unequal split-K — 128 big tiles (K-chunks 0..99) fill 128 SMs while
// 128 small tiles (chunks 100..111) backfill the 20 idle SMs. Deterministic
// fixed-order partial sum in topk.
// Output (float32): [ T*8 indices (as float) | T*8 weights ]
// ============================================================================

#define N_EXPERTS 256
#define TOPK_GRP  4
#define TOP_K     8
#define SCALE     2.5f
#define H_DIM     7168
#define MAX_T     8192
#define W_PRESCALE   64.0f
#define W_POSTSCALE  0.015625f   // 1/64

__device__ float g_logits [MAX_T * N_EXPERTS];                // big partials
__device__ float g_logits2[MAX_T * N_EXPERTS];                // small partials
__device__ __align__(16) __half g_wh[N_EXPERTS * H_DIM];      // fp16(64*w)
__device__ __align__(16) __half g_wm[N_EXPERTS * H_DIM];      // fp16(64*w - hi)

// ---------------------------------------------------------------------------
// helpers
// ---------------------------------------------------------------------------
__device__ __forceinline__ uint32_t smem_to_u32(const void* p) {
    uint32_t a;
    asm("{ .reg .u64 t; cvta.to.shared.u64 t, %1; cvt.u32.u64 %0, t; }"
        : "=r"(a) : "l"(p));
    return a;
}
__device__ __forceinline__ void cp16(uint32_t dst, const void* src) {
    asm volatile("cp.async.cg.shared.global [%0], [%1], 16;" :: "r"(dst), "l"(src));
}
#define CP_COMMIT() asm volatile("cp.async.commit_group;" ::: "memory")
#define CP_WAIT1()  asm volatile("cp.async.wait_group 1;" ::: "memory")

__device__ __forceinline__ void ldmatrix_x4(uint32_t* r, uint32_t addr) {
    asm volatile("ldmatrix.sync.aligned.m8n8.x4.shared.b16 {%0,%1,%2,%3}, [%4];"
                 : "=r"(r[0]), "=r"(r[1]), "=r"(r[2]), "=r"(r[3]) : "r"(addr));
}
__device__ __forceinline__ void mma_fp16(float* d, const uint32_t* a,
                                         uint32_t b0, uint32_t b1) {
    asm volatile(
        "mma.sync.aligned.m16n8k16.row.col.f32.f16.f16.f32 "
        "{%0,%1,%2,%3}, {%4,%5,%6,%7}, {%8,%9}, {%0,%1,%2,%3};"
        : "+f"(d[0]), "+f"(d[1]), "+f"(d[2]), "+f"(d[3])
        : "r"(a[0]), "r"(a[1]), "r"(a[2]), "r"(a[3]), "r"(b0), "r"(b1));
}

// split a float2 into 2 packed fp16x2 (hi, mid); low 16 bits = f.x
__device__ __forceinline__ void split2(float2 f, uint32_t& h, uint32_t& m) {
    __half2 hh = __floats2half2_rn(f.x, f.y);
    h = *reinterpret_cast<uint32_t*>(&hh);
    float2 hf = __half22float2(hh);
    __half2 mm2 = __floats2half2_rn(f.x - hf.x, f.y - hf.y);
    m = *reinterpret_cast<uint32_t*>(&mm2);
}

// monotone float <-> unsigned-comparable key
__device__ __forceinline__ unsigned f2ord(float f) {
    unsigned u = __float_as_uint(f);
    return u ^ ((((int)u) >> 31) | 0x80000000u);
}
__device__ __forceinline__ float ord2f(unsigned k) {
    unsigned u = (k & 0x80000000u) ? (k ^ 0x80000000u) : ~k;
    return __uint_as_float(u);
}

// ---------------------------------------------------------------------------
// Kernel 0: split prescaled fp32 weights -> 2 fp16 tensors (2 float4/thread)
// ---------------------------------------------------------------------------
__global__ __launch_bounds__(256)
void split_w_kernel(const float* __restrict__ w)
{
    const int n4 = N_EXPERTS * H_DIM / 4;
    int base = blockIdx.x * 512 + threadIdx.x;
#pragma unroll
    for (int r = 0; r < 2; r++) {
        int i = base + r * 256;
        if (i >= n4) break;
        float4 v = reinterpret_cast<const float4*>(w)[i];
        uint32_t h0, m0, h1, m1;
        split2(make_float2(v.x * W_PRESCALE, v.y * W_PRESCALE), h0, m0);
        split2(make_float2(v.z * W_PRESCALE, v.w * W_PRESCALE), h1, m1);
        reinterpret_cast<uint2*>(g_wh)[i] = make_uint2(h0, h1);
        reinterpret_cast<uint2*>(g_wm)[i] = make_uint2(m0, m1);
    }
}

// ---------------------------------------------------------------------------
// Kernel 1: GEMM via mma.sync fp16x2, 3 passes, single accumulator + RN flush.
// CTA tile: 128 tokens x 128 experts, but split in K:
//   bid 0..127  : big   segment, chunks [0, BIGC)
//   bid 128..255: small segment, chunks [BIGC, NCHUNK)
// BK=64. 3-stage cp.async pipeline. 1 CTA/SM (mainloop identical to R7).
// ---------------------------------------------------------------------------
#define BM        128
#define BN        128
#define BK        64
#define NCHUNK    (H_DIM / BK)          // 112
#define BIGC      100                   // big segment: chunks 0..99 (K=6400)
#define FLUSH_MASK 3                    // flush every 4 local chunks (K=256)
#define A_ROWB    288                   // 72 floats
#define A_BYTES   (128 * A_ROWB)        // 36864
#define B_ROWB    144
#define B_SPLIT_B (128 * B_ROWB)        // 18432
#define STAGE_B   (A_BYTES + 2 * B_SPLIT_B)  // 73728
#define GEMM_SMEM (3 * STAGE_B)              // 221184

__device__ __forceinline__ void load_stage(const float* __restrict__ x,
                                           int row0, int e0, int k0,
                                           uint32_t stage_base, int tid)
{
    // A: 128 rows x 64 fp32 (256B payload/row, stride 288B): 2048 cp16
#pragma unroll
    for (int l = 0; l < 8; l++) {
        int q = tid + 256 * l;             // 0..2047
        int row = q >> 4, seg = q & 15;
        const float* src = x + (size_t)(row0 + row) * H_DIM + k0 + seg * 4;
        cp16(stage_base + row * A_ROWB + seg * 16, src);
    }
    // B: 2 splits x 128 rows x 64 fp16 (128B payload/row, stride 144B): 2048 cp16
#pragma unroll
    for (int l = 0; l < 8; l++) {
        int q = tid + 256 * l;             // 0..2047
        int s = q >> 10;                   // split
        int r = q & 1023;
        int row = r >> 3, seg = r & 7;
        const __half* wp = s ? g_wm : g_wh;
        const __half* src = wp + (size_t)(e0 + row) * H_DIM + k0 + seg * 8;
        cp16(stage_base + A_BYTES + s * B_SPLIT_B + row * B_ROWB + seg * 16, src);
    }
}

__global__ __launch_bounds__(256, 1)
void moe_gemm_mma(const float* __restrict__ x)
{
    extern __shared__ char smem[];
    const uint32_t sbase = smem_to_u32(smem);
    const int tid  = threadIdx.x;
    const int lane = tid & 31;
    const int wid  = tid >> 5;
    const int wm   = wid & 3;              // warp row (m)
    const int wn   = wid >> 2;             // warp col (n)

    const int bid  = blockIdx.x;
    const bool big = bid < 128;
    const int tile = big ? bid : bid - 128;
    const int row0 = (tile >> 1) * BM;
    const int e0   = (tile & 1) * BN;
    const int c0   = big ? 0 : BIGC;       // first chunk (inclusive)
    const int cn   = big ? BIGC : NCHUNK;  // last chunk (exclusive)
    float* dst = big ? g_logits : g_logits2;

    float acc[2][8][4];                    // short-chain accumulators
    float master[2][8][4];                 // RN-summed masters
#pragma unroll
    for (int mt = 0; mt < 2; mt++)
#pragma unroll
        for (int nt = 0; nt < 8; nt++)
#pragma unroll
            for (int q = 0; q < 4; q++) { acc[mt][nt][q] = 0.0f; master[mt][nt][q] = 0.0f; }

    // prologue: stages c0, c0+1
    load_stage(x, row0, e0, c0 * BK,       sbase + 0 * STAGE_B, tid); CP_COMMIT();
    load_stage(x, row0, e0, (c0 + 1) * BK, sbase + 1 * STAGE_B, tid); CP_COMMIT();

    const int c2 = (lane & 3) * 2;         // k-pair base within 8

    for (int lc = 0; lc < cn - c0; ++lc) { // local chunk index
        const int c = c0 + lc;
        CP_WAIT1();
        __syncthreads();

        if (c + 2 < cn)
            load_stage(x, row0, e0, (c + 2) * BK, sbase + ((lc + 2) % 3) * STAGE_B, tid);
        CP_COMMIT();

        const int slot = lc % 3;
        const char* As = smem + slot * STAGE_B;
        const uint32_t Bs = sbase + slot * STAGE_B + A_BYTES;

#pragma unroll
        for (int kk = 0; kk < 4; kk++) {           // four k16 steps per BK=64
            // ---- A fragments: load fp32 pairs, split to fp16x2 ----
            uint32_t ah[2][4], am[2][4];
#pragma unroll
            for (int mt = 0; mt < 2; mt++) {
                int brow = wm * 32 + mt * 16 + (lane >> 2);
#pragma unroll
                for (int q = 0; q < 4; q++) {
                    int r   = brow + (q & 1) * 8;
                    int col = kk * 16 + c2 + (q >> 1) * 8;
                    float2 f = *reinterpret_cast<const float2*>(As + r * A_ROWB + col * 4);
                    split2(f, ah[mt][q], am[mt][q]);
                }
            }
            // ---- 3 passes: s=0 -> ah*bh + am*bh ; s=1 -> ah*bm ----
#pragma unroll
            for (int s = 0; s < 2; s++) {
                uint32_t b[4][4];
#pragma unroll
                for (int p = 0; p < 4; p++) {
                    int row = wn * 64 + p * 16 + (lane & 7) + ((lane >> 4) & 1) * 8;
                    uint32_t addr = Bs + s * B_SPLIT_B + row * B_ROWB
                                  + kk * 32 + ((lane >> 3) & 1) * 16;
                    ldmatrix_x4(b[p], addr);
                }
#pragma unroll
                for (int mt = 0; mt < 2; mt++)
#pragma unroll
                    for (int nt = 0; nt < 8; nt++) {
                        int p = nt >> 1, o = (nt & 1) * 2;
                        mma_fp16(acc[mt][nt], ah[mt], b[p][o], b[p][o + 1]);
                    }
                if (s == 0) {
#pragma unroll
                    for (int mt = 0; mt < 2; mt++)
#pragma unroll
                        for (int nt = 0; nt < 8; nt++) {
                            int p = nt >> 1, o = (nt & 1) * 2;
                            mma_fp16(acc[mt][nt], am[mt], b[p][o], b[p][o + 1]);
                        }
                }
            }
        }

        // ---- RN flush: keep tensor-core accumulation chains short ----
        if ((lc & FLUSH_MASK) == FLUSH_MASK) {
#pragma unroll
            for (int mt = 0; mt < 2; mt++)
#pragma unroll
                for (int nt = 0; nt < 8; nt++)
#pragma unroll
                    for (int q = 0; q < 4; q++) {
                        master[mt][nt][q] += acc[mt][nt][q];
                        acc[mt][nt][q] = 0.0f;
                    }
        }
    }

    // fold residual chunks (segment length may not be multiple of 4)
#pragma unroll
    for (int mt = 0; mt < 2; mt++)
#pragma unroll
        for (int nt = 0; nt < 8; nt++)
#pragma unroll
            for (int q = 0; q < 4; q++) master[mt][nt][q] += acc[mt][nt][q];

    // epilogue: write partial logits (undo W prescale)
#pragma unroll
    for (int mt = 0; mt < 2; mt++) {
        int row = row0 + wm * 32 + mt * 16 + (lane >> 2);
#pragma unroll
        for (int nt = 0; nt < 8; nt++) {
            int col = e0 + wn * 64 + nt * 8 + c2;
            *reinterpret_cast<float2*>(&dst[(size_t)row * N_EXPERTS + col]) =
                make_float2(master[mt][nt][0] * W_POSTSCALE,
                            master[mt][nt][1] * W_POSTSCALE);
            *reinterpret_cast<float2*>(&dst[(size_t)(row + 8) * N_EXPERTS + col]) =
                make_float2(master[mt][nt][2] * W_POSTSCALE,
                            master[mt][nt][3] * W_POSTSCALE);
        }
    }
}

// ---------------------------------------------------------------------------
// Kernel 2: per-token grouped top-k. One warp per token.
// Sums the two K-partials in fixed order (deterministic).
// ---------------------------------------------------------------------------
__global__ __launch_bounds__(256)
void moe_topk_kernel(const float* __restrict__ bias, float* __restrict__ out, int T)
{
    const unsigned FULL = 0xFFFFFFFFu;
    const int lane   = threadIdx.x & 31;
    const int warpId = threadIdx.x >> 5;
    const int t = blockIdx.x * 8 + warpId;
    if (t >= T) return;

    const float* lg  = &g_logits [(size_t)t * N_EXPERTS];
    const float* lg2 = &g_logits2[(size_t)t * N_EXPERTS];

    float s[8], sb[8];
#pragma unroll
    for (int j = 0; j < 8; j++) {
        int e = j * 32 + lane;
        float logit = lg[e] + lg2[e];
        float sv = 1.0f / (1.0f + __expf(-logit));
        s[j]  = sv;
        sb[j] = sv + bias[e];
    }

    // per-group top-2 sum via REDUX (sum is tie-insensitive)
    float gs[8];
#pragma unroll
    for (int g = 0; g < 8; g++) {
        unsigned k = f2ord(sb[g]);
        unsigned m1 = __reduce_max_sync(FULL, k);
        unsigned bal = __ballot_sync(FULL, k == m1);
        int leader = __ffs(bal) - 1;
        unsigned k2 = (lane == leader) ? 0u : k;
        unsigned m2 = __reduce_max_sync(FULL, k2);
        gs[g] = ord2f(m1) + ord2f(m2);
    }

    unsigned gmask = 0;
#pragma unroll
    for (int r = 0; r < TOPK_GRP; r++) {
        float best = -FLT_MAX; int bg = 0;
#pragma unroll
        for (int g = 0; g < 8; g++) {
            bool taken = (gmask >> g) & 1u;
            if (!taken && gs[g] > best) { best = gs[g]; bg = g; }
        }
        gmask |= (1u << bg);
    }

    float v[8];
#pragma unroll
    for (int j = 0; j < 8; j++)
        v[j] = ((gmask >> j) & 1u) ? sb[j] : -FLT_MAX;

    float wts[TOP_K];
    int   idxs[TOP_K];
    float wsum = 0.0f;
#pragma unroll
    for (int r = 0; r < TOP_K; r++) {
        float bv = -FLT_MAX; int bj = -1;
#pragma unroll
        for (int j = 0; j < 8; j++)
            if (v[j] > bv) { bv = v[j]; bj = j; }
        int bidx = (bj >= 0) ? (bj * 32 + lane) : (N_EXPERTS + lane);

        float cv = bv; int ci = bidx;
#pragma unroll
        for (int off = 16; off >= 1; off >>= 1) {
            float ov = __shfl_xor_sync(FULL, cv, off);
            int   oi = __shfl_xor_sync(FULL, ci, off);
            if (ov > cv || (ov == cv && oi < ci)) { cv = ov; ci = oi; }
        }
        int wl = ci & 31;
        int wj = ci >> 5;
        float sv_local = 0.0f;
#pragma unroll
        for (int j = 0; j < 8; j++) if (j == wj) sv_local = s[j];
        float sv = __shfl_sync(FULL, sv_local, wl);

        idxs[r] = ci;
        wts[r]  = sv;
        wsum   += sv;

        if (lane == wl) {
#pragma unroll
            for (int j = 0; j < 8; j++) if (j == wj) v[j] = -FLT_MAX;
        }
    }

    if (lane == 0) {
        float inv = SCALE / wsum;
        size_t half = (size_t)T * TOP_K;
#pragma unroll
        for (int r = 0; r < TOP_K; r++) {
            out[(size_t)t * TOP_K + r]        = (float)idxs[r];
            out[half + (size_t)t * TOP_K + r] = wts[r] * inv;
        }
    }
}

// ---------------------------------------------------------------------------
extern "C" void kernel_launch(void* const* d_in, const int* in_sizes, int n_in,
                              void* d_out, int out_size)
{
    const float* x    = (const float*)d_in[0];   // [B,S,H] fp32
    const float* w    = (const float*)d_in[1];   // [E,H]   fp32
    const float* bias = (const float*)d_in[2];   // [E]     fp32
    float* out = (float*)d_out;

    const int E = in_sizes[2];                   // 256
    const int H = in_sizes[1] / E;               // 7168
    const int T = in_sizes[0] / H;               // 8192

    // 0) split prescaled weights into fp16x2 (2 float4 per thread)
    {
        int n4 = E * H / 4;
        split_w_kernel<<<(n4 + 511) / 512, 256>>>(w);
    }

    // 1) tensor-core GEMM -> g_logits (+ g_logits2 small-K partials)
    cudaFuncSetAttribute(moe_gemm_mma,
                         cudaFuncAttributeMaxDynamicSharedMemorySize, GEMM_SMEM);
    moe_gemm_mma<<<256, 256, GEMM_SMEM>>>(x);    // 128 big + 128 small CTAs

    // 2) grouped top-k (fixed-order partial sum -> deterministic)
    dim3 topkGrid((T + 7) / 8);
    moe_topk_kernel<<<topkGrid, 256>>>(bias, out, T);
}

// round 13
// speedup vs baseline: 1.4378x; 1.0148x over previous
#include <cuda_runtime.h>
#include <cuda_fp16.h>
#include <math.h>
#include <float.h>
#include <stdint.h>

// ============================================================================
// DeepSeekV3 MoE Gate (sm_103a; PTX target compute_103 -> no tcgen05).
// GEMM via mma.sync.m16n8k16 fp16, fp16x2 split, 3 passes (hh, hm, mh),
// W prescaled x64 (single fp32 accumulator), periodic RN master flush.
// R12 split-K layout kept: 128 big tiles (K-chunks 0..99) + 128 small tiles
// (chunks 100..111) backfilling the 20 otherwise-idle SMs.
// R13: topk argmax via REDUX (precomputed monotone keys), split_w ILP x4.
// Output (float32): [ T*8 indices (as float) | T*8 weights ]
// ============================================================================

#define N_EXPERTS 256
#define TOPK_GRP  4
#define TOP_K     8
#define SCALE     2.5f
#define H_DIM     7168
#define MAX_T     8192
#define W_PRESCALE   64.0f
#define W_POSTSCALE  0.015625f   // 1/64

__device__ float g_logits [MAX_T * N_EXPERTS];                // big partials
__device__ float g_logits2[MAX_T * N_EXPERTS];                // small partials
__device__ __align__(16) __half g_wh[N_EXPERTS * H_DIM];      // fp16(64*w)
__device__ __align__(16) __half g_wm[N_EXPERTS * H_DIM];      // fp16(64*w - hi)

// ---------------------------------------------------------------------------
// helpers
// ---------------------------------------------------------------------------
__device__ __forceinline__ uint32_t smem_to_u32(const void* p) {
    uint32_t a;
    asm("{ .reg .u64 t; cvta.to.shared.u64 t, %1; cvt.u32.u64 %0, t; }"
        : "=r"(a) : "l"(p));
    return a;
}
__device__ __forceinline__ void cp16(uint32_t dst, const void* src) {
    asm volatile("cp.async.cg.shared.global [%0], [%1], 16;" :: "r"(dst), "l"(src));
}
#define CP_COMMIT() asm volatile("cp.async.commit_group;" ::: "memory")
#define CP_WAIT1()  asm volatile("cp.async.wait_group 1;" ::: "memory")

__device__ __forceinline__ void ldmatrix_x4(uint32_t* r, uint32_t addr) {
    asm volatile("ldmatrix.sync.aligned.m8n8.x4.shared.b16 {%0,%1,%2,%3}, [%4];"
                 : "=r"(r[0]), "=r"(r[1]), "=r"(r[2]), "=r"(r[3]) : "r"(addr));
}
__device__ __forceinline__ void mma_fp16(float* d, const uint32_t* a,
                                         uint32_t b0, uint32_t b1) {
    asm volatile(
        "mma.sync.aligned.m16n8k16.row.col.f32.f16.f16.f32 "
        "{%0,%1,%2,%3}, {%4,%5,%6,%7}, {%8,%9}, {%0,%1,%2,%3};"
        : "+f"(d[0]), "+f"(d[1]), "+f"(d[2]), "+f"(d[3])
        : "r"(a[0]), "r"(a[1]), "r"(a[2]), "r"(a[3]), "r"(b0), "r"(b1));
}

// split a float2 into 2 packed fp16x2 (hi, mid); low 16 bits = f.x
__device__ __forceinline__ void split2(float2 f, uint32_t& h, uint32_t& m) {
    __half2 hh = __floats2half2_rn(f.x, f.y);
    h = *reinterpret_cast<uint32_t*>(&hh);
    float2 hf = __half22float2(hh);
    __half2 mm2 = __floats2half2_rn(f.x - hf.x, f.y - hf.y);
    m = *reinterpret_cast<uint32_t*>(&mm2);
}

// monotone float <-> unsigned-comparable key (finite inputs map to key > 0)
__device__ __forceinline__ unsigned f2ord(float f) {
    unsigned u = __float_as_uint(f);
    return u ^ ((((int)u) >> 31) | 0x80000000u);
}
__device__ __forceinline__ float ord2f(unsigned k) {
    unsigned u = (k & 0x80000000u) ? (k ^ 0x80000000u) : ~k;
    return __uint_as_float(u);
}

// ---------------------------------------------------------------------------
// Kernel 0: split prescaled fp32 weights -> 2 fp16 tensors (4 float4/thread)
// ---------------------------------------------------------------------------
__global__ __launch_bounds__(256)
void split_w_kernel(const float* __restrict__ w)
{
    const int n4 = N_EXPERTS * H_DIM / 4;
    int base = blockIdx.x * 1024 + threadIdx.x;
    float4 v[4];
    int idx[4];
#pragma unroll
    for (int r = 0; r < 4; r++) {
        idx[r] = base + r * 256;
        if (idx[r] < n4) v[r] = reinterpret_cast<const float4*>(w)[idx[r]];
    }
#pragma unroll
    for (int r = 0; r < 4; r++) {
        if (idx[r] >= n4) break;
        uint32_t h0, m0, h1, m1;
        split2(make_float2(v[r].x * W_PRESCALE, v[r].y * W_PRESCALE), h0, m0);
        split2(make_float2(v[r].z * W_PRESCALE, v[r].w * W_PRESCALE), h1, m1);
        reinterpret_cast<uint2*>(g_wh)[idx[r]] = make_uint2(h0, h1);
        reinterpret_cast<uint2*>(g_wm)[idx[r]] = make_uint2(m0, m1);
    }
}

// ---------------------------------------------------------------------------
// Kernel 1: GEMM via mma.sync fp16x2, 3 passes, single accumulator + RN flush.
// CTA tile: 128 tokens x 128 experts, split in K:
//   bid 0..127  : big   segment, chunks [0, BIGC)
//   bid 128..255: small segment, chunks [BIGC, NCHUNK)
// BK=64. 3-stage cp.async pipeline. 1 CTA/SM. (PROVEN — do not modify.)
// ---------------------------------------------------------------------------
#define BM        128
#define BN        128
#define BK        64
#define NCHUNK    (H_DIM / BK)          // 112
#define BIGC      100                   // big segment: chunks 0..99 (K=6400)
#define FLUSH_MASK 3                    // flush every 4 local chunks (K=256)
#define A_ROWB    288                   // 72 floats
#define A_BYTES   (128 * A_ROWB)        // 36864
#define B_ROWB    144
#define B_SPLIT_B (128 * B_ROWB)        // 18432
#define STAGE_B   (A_BYTES + 2 * B_SPLIT_B)  // 73728
#define GEMM_SMEM (3 * STAGE_B)              // 221184

__device__ __forceinline__ void load_stage(const float* __restrict__ x,
                                           int row0, int e0, int k0,
                                           uint32_t stage_base, int tid)
{
    // A: 128 rows x 64 fp32 (256B payload/row, stride 288B): 2048 cp16
#pragma unroll
    for (int l = 0; l < 8; l++) {
        int q = tid + 256 * l;             // 0..2047
        int row = q >> 4, seg = q & 15;
        const float* src = x + (size_t)(row0 + row) * H_DIM + k0 + seg * 4;
        cp16(stage_base + row * A_ROWB + seg * 16, src);
    }
    // B: 2 splits x 128 rows x 64 fp16 (128B payload/row, stride 144B): 2048 cp16
#pragma unroll
    for (int l = 0; l < 8; l++) {
        int q = tid + 256 * l;             // 0..2047
        int s = q >> 10;                   // split
        int r = q & 1023;
        int row = r >> 3, seg = r & 7;
        const __half* wp = s ? g_wm : g_wh;
        const __half* src = wp + (size_t)(e0 + row) * H_DIM + k0 + seg * 8;
        cp16(stage_base + A_BYTES + s * B_SPLIT_B + row * B_ROWB + seg * 16, src);
    }
}

__global__ __launch_bounds__(256, 1)
void moe_gemm_mma(const float* __restrict__ x)
{
    extern __shared__ char smem[];
    const uint32_t sbase = smem_to_u32(smem);
    const int tid  = threadIdx.x;
    const int lane = tid & 31;
    const int wid  = tid >> 5;
    const int wm   = wid & 3;              // warp row (m)
    const int wn   = wid >> 2;             // warp col (n)

    const int bid  = blockIdx.x;
    const bool big = bid < 128;
    const int tile = big ? bid : bid - 128;
    const int row0 = (tile >> 1) * BM;
    const int e0   = (tile & 1) * BN;
    const int c0   = big ? 0 : BIGC;       // first chunk (inclusive)
    const int cn   = big ? BIGC : NCHUNK;  // last chunk (exclusive)
    float* dst = big ? g_logits : g_logits2;

    float acc[2][8][4];                    // short-chain accumulators
    float master[2][8][4];                 // RN-summed masters
#pragma unroll
    for (int mt = 0; mt < 2; mt++)
#pragma unroll
        for (int nt = 0; nt < 8; nt++)
#pragma unroll
            for (int q = 0; q < 4; q++) { acc[mt][nt][q] = 0.0f; master[mt][nt][q] = 0.0f; }

    // prologue: stages c0, c0+1
    load_stage(x, row0, e0, c0 * BK,       sbase + 0 * STAGE_B, tid); CP_COMMIT();
    load_stage(x, row0, e0, (c0 + 1) * BK, sbase + 1 * STAGE_B, tid); CP_COMMIT();

    const int c2 = (lane & 3) * 2;         // k-pair base within 8

    for (int lc = 0; lc < cn - c0; ++lc) { // local chunk index
        const int c = c0 + lc;
        CP_WAIT1();
        __syncthreads();

        if (c + 2 < cn)
            load_stage(x, row0, e0, (c + 2) * BK, sbase + ((lc + 2) % 3) * STAGE_B, tid);
        CP_COMMIT();

        const int slot = lc % 3;
        const char* As = smem + slot * STAGE_B;
        const uint32_t Bs = sbase + slot * STAGE_B + A_BYTES;

#pragma unroll
        for (int kk = 0; kk < 4; kk++) {           // four k16 steps per BK=64
            // ---- A fragments: load fp32 pairs, split to fp16x2 ----
            uint32_t ah[2][4], am[2][4];
#pragma unroll
            for (int mt = 0; mt < 2; mt++) {
                int brow = wm * 32 + mt * 16 + (lane >> 2);
#pragma unroll
                for (int q = 0; q < 4; q++) {
                    int r   = brow + (q & 1) * 8;
                    int col = kk * 16 + c2 + (q >> 1) * 8;
                    float2 f = *reinterpret_cast<const float2*>(As + r * A_ROWB + col * 4);
                    split2(f, ah[mt][q], am[mt][q]);
                }
            }
            // ---- 3 passes: s=0 -> ah*bh + am*bh ; s=1 -> ah*bm ----
#pragma unroll
            for (int s = 0; s < 2; s++) {
                uint32_t b[4][4];
#pragma unroll
                for (int p = 0; p < 4; p++) {
                    int row = wn * 64 + p * 16 + (lane & 7) + ((lane >> 4) & 1) * 8;
                    uint32_t addr = Bs + s * B_SPLIT_B + row * B_ROWB
                                  + kk * 32 + ((lane >> 3) & 1) * 16;
                    ldmatrix_x4(b[p], addr);
                }
#pragma unroll
                for (int mt = 0; mt < 2; mt++)
#pragma unroll
                    for (int nt = 0; nt < 8; nt++) {
                        int p = nt >> 1, o = (nt & 1) * 2;
                        mma_fp16(acc[mt][nt], ah[mt], b[p][o], b[p][o + 1]);
                    }
                if (s == 0) {
#pragma unroll
                    for (int mt = 0; mt < 2; mt++)
#pragma unroll
                        for (int nt = 0; nt < 8; nt++) {
                            int p = nt >> 1, o = (nt & 1) * 2;
                            mma_fp16(acc[mt][nt], am[mt], b[p][o], b[p][o + 1]);
                        }
                }
            }
        }

        // ---- RN flush: keep tensor-core accumulation chains short ----
        if ((lc & FLUSH_MASK) == FLUSH_MASK) {
#pragma unroll
            for (int mt = 0; mt < 2; mt++)
#pragma unroll
                for (int nt = 0; nt < 8; nt++)
#pragma unroll
                    for (int q = 0; q < 4; q++) {
                        master[mt][nt][q] += acc[mt][nt][q];
                        acc[mt][nt][q] = 0.0f;
                    }
        }
    }

    // fold residual chunks (segment length may not be multiple of 4)
#pragma unroll
    for (int mt = 0; mt < 2; mt++)
#pragma unroll
        for (int nt = 0; nt < 8; nt++)
#pragma unroll
            for (int q = 0; q < 4; q++) master[mt][nt][q] += acc[mt][nt][q];

    // epilogue: write partial logits (undo W prescale)
#pragma unroll
    for (int mt = 0; mt < 2; mt++) {
        int row = row0 + wm * 32 + mt * 16 + (lane >> 2);
#pragma unroll
        for (int nt = 0; nt < 8; nt++) {
            int col = e0 + wn * 64 + nt * 8 + c2;
            *reinterpret_cast<float2*>(&dst[(size_t)row * N_EXPERTS + col]) =
                make_float2(master[mt][nt][0] * W_POSTSCALE,
                            master[mt][nt][1] * W_POSTSCALE);
            *reinterpret_cast<float2*>(&dst[(size_t)(row + 8) * N_EXPERTS + col]) =
                make_float2(master[mt][nt][2] * W_POSTSCALE,
                            master[mt][nt][3] * W_POSTSCALE);
        }
    }
}

// ---------------------------------------------------------------------------
// Kernel 2: per-token grouped top-k. One warp per token.
// R13: precomputed monotone keys + REDUX max/min argmax rounds.
// Tie semantics preserved exactly: value desc, tie -> lowest expert index
// (reduce_min over indices among max-key holders).
// ---------------------------------------------------------------------------
__global__ __launch_bounds__(256)
void moe_topk_kernel(const float* __restrict__ bias, float* __restrict__ out, int T)
{
    const unsigned FULL = 0xFFFFFFFFu;
    const int lane   = threadIdx.x & 31;
    const int warpId = threadIdx.x >> 5;
    const int t = blockIdx.x * 8 + warpId;
    if (t >= T) return;

    const float* lg  = &g_logits [(size_t)t * N_EXPERTS];
    const float* lg2 = &g_logits2[(size_t)t * N_EXPERTS];

    float s[8];
    unsigned k[8];                         // monotone keys of sb (all > 0)
#pragma unroll
    for (int j = 0; j < 8; j++) {
        int e = j * 32 + lane;
        float logit = lg[e] + lg2[e];      // fixed-order partial sum
        float sv = 1.0f / (1.0f + __expf(-logit));
        s[j] = sv;
        k[j] = f2ord(sv + bias[e]);
    }

    // per-group top-2 sum via REDUX (sum is tie-insensitive)
    float gs[8];
#pragma unroll
    for (int g = 0; g < 8; g++) {
        unsigned m1 = __reduce_max_sync(FULL, k[g]);
        unsigned bal = __ballot_sync(FULL, k[g] == m1);
        int leader = __ffs(bal) - 1;
        unsigned k2 = (lane == leader) ? 0u : k[g];
        unsigned m2 = __reduce_max_sync(FULL, k2);
        gs[g] = ord2f(m1) + ord2f(m2);
    }

    unsigned gmask = 0;
#pragma unroll
    for (int r = 0; r < TOPK_GRP; r++) {
        float best = -FLT_MAX; int bg = 0;
#pragma unroll
        for (int g = 0; g < 8; g++) {
            bool taken = (gmask >> g) & 1u;
            if (!taken && gs[g] > best) { best = gs[g]; bg = g; }
        }
        gmask |= (1u << bg);
    }

    // candidate keys: 0 = removed/inactive (all real keys > 0)
    unsigned kv[8];
#pragma unroll
    for (int j = 0; j < 8; j++)
        kv[j] = ((gmask >> j) & 1u) ? k[j] : 0u;

    float wts[TOP_K];
    int   idxs[TOP_K];
    float wsum = 0.0f;
#pragma unroll
    for (int r = 0; r < TOP_K; r++) {
        // lane-local max key
        unsigned kb = kv[0];
#pragma unroll
        for (int j = 1; j < 8; j++) kb = kb > kv[j] ? kb : kv[j];
        // warp max key
        unsigned m = __reduce_max_sync(FULL, kb);
        // lowest expert index holding key m (descending j -> final = smallest j)
        int myidx = 0x7FFFFFFF;
#pragma unroll
        for (int j = 7; j >= 0; j--)
            if (kv[j] == m) myidx = j * 32 + lane;
        int widx = __reduce_min_sync(FULL, myidx);

        int wl = widx & 31;
        int wj = widx >> 5;
        float sv_local = 0.0f;
#pragma unroll
        for (int j = 0; j < 8; j++) if (j == wj) sv_local = s[j];
        float sv = __shfl_sync(FULL, sv_local, wl);

        idxs[r] = widx;
        wts[r]  = sv;
        wsum   += sv;

        if (lane == wl) {
#pragma unroll
            for (int j = 0; j < 8; j++) if (j == wj) kv[j] = 0u;
        }
    }

    if (lane == 0) {
        float inv = SCALE / wsum;
        size_t half = (size_t)T * TOP_K;
#pragma unroll
        for (int r = 0; r < TOP_K; r++) {
            out[(size_t)t * TOP_K + r]        = (float)idxs[r];
            out[half + (size_t)t * TOP_K + r] = wts[r] * inv;
        }
    }
}

// ---------------------------------------------------------------------------
extern "C" void kernel_launch(void* const* d_in, const int* in_sizes, int n_in,
                              void* d_out, int out_size)
{
    const float* x    = (const float*)d_in[0];   // [B,S,H] fp32
    const float* w    = (const float*)d_in[1];   // [E,H]   fp32
    const float* bias = (const float*)d_in[2];   // [E]     fp32
    float* out = (float*)d_out;

    const int E = in_sizes[2];                   // 256
    const int H = in_sizes[1] / E;               // 7168
    const int T = in_sizes[0] / H;               // 8192

    // 0) split prescaled weights into fp16x2 (4 float4 per thread)
    {
        int n4 = E * H / 4;
        split_w_kernel<<<(n4 + 1023) / 1024, 256>>>(w);
    }

    // 1) tensor-core GEMM -> g_logits (+ g_logits2 small-K partials)
    cudaFuncSetAttribute(moe_gemm_mma,
                         cudaFuncAttributeMaxDynamicSharedMemorySize, GEMM_SMEM);
    moe_gemm_mma<<<256, 256, GEMM_SMEM>>>(x);    // 128 big + 128 small CTAs

    // 2) grouped top-k (fixed-order partial sum -> deterministic)
    dim3 topkGrid((T + 7) / 8);
    moe_topk_kernel<<<topkGrid, 256>>>(bias, out, T);
}